// round 17
// baseline (speedup 1.0000x reference)
#include <cuda_runtime.h>
#include <math.h>

#define NBATCH 2048

// ---- image layout: plain rows, stride 68 (=17 float4), x stored at idx x+2 ----
// row ry = y+2 (0..66, rows 0,1,66 zero), idx 0,1,66,67 zero pad
// pixel ox: taps = floats 4*ox .. 4*ox+10
#define IMROW 68
#define IMCH  (67 * IMROW)          // 4556 (mult of 4 -> float4-aligned rows)
#define S_W1  13668                 // conv1 weights [c][ky][f][12] = 3960 (float4-aligned)
#define SMEM_FLOATS (S_W1 + 3960)   // 17628 floats = 70512 bytes -> 3 CTAs/SM

// aliases in the image region (dead after conv1 mainloop):
#define S_TMP  0                    // group-B partials [10][15][16] = 2400
#define S_C1   2400                 // conv1 out [10][15][16] = 2400
#define S_W2P  4800                 // conv2 weights padded [16][10][5][8] = 6400
#define S_P1P  11200                // pool1 out zero-padded [10][11][12] = 1320
#define S_C2   12520                // conv2 out [16][4][4] = 256
#define S_FL   12776                // flat 64 (total 12840 < 13668 ✓)

__device__ __forceinline__ float leaky(float v) { return v > 0.f ? v : 0.01f * v; }

__device__ __forceinline__ unsigned long long pack2(float lo, float hi) {
    unsigned long long r;
    asm("mov.b64 %0, {%1, %2};" : "=l"(r) : "f"(lo), "f"(hi));
    return r;
}
__device__ __forceinline__ void fma2(unsigned long long& d, unsigned long long a,
                                     unsigned long long b) {
    asm("fma.rn.f32x2 %0, %1, %2, %0;" : "+l"(d) : "l"(a), "l"(b));
}
__device__ __forceinline__ void unpack2(unsigned long long v, float& lo, float& hi) {
    asm("mov.b64 {%0, %1}, %2;" : "=f"(lo), "=f"(hi) : "l"(v));
}

// one (c,ky) reduction row of conv1: 5 filters x 4 adjacent pixels as 2 f32x2 pairs
// acc[f][0] = {d0,d1}, acc[f][1] = {d2,d3}
__device__ __forceinline__ void c1_row(const float* __restrict__ sm,
                                       int c, int ky, int oy, int pr, int fh,
                                       unsigned long long acc[5][2])
{
    const float4* row = (const float4*)&sm[c * IMCH + (4 * oy + ky) * IMROW] + 4 * pr;
    float4 X[6];
    #pragma unroll
    for (int j = 0; j < 6; j++) X[j] = row[j];
    const float* xs = (const float*)X;   // pixel d taps = xs[4d+k], k=0..10
    const float* wr = &sm[S_W1 + (c * 11 + ky) * 120 + fh * 60];

    // k-chunks of 4 taps bound live registers (xp arrays reused per chunk)
    #pragma unroll
    for (int kc = 0; kc < 3; kc++) {
        const int kb = kc * 4;
        const int ke = (kc == 2) ? 3 : 4;    // taps 0-3,4-7,8-10
        unsigned long long xp0[4], xp1[4];
        #pragma unroll
        for (int kk = 0; kk < 4; kk++) {
            if (kk < ke) {
                xp0[kk] = pack2(xs[kb + kk],     xs[kb + kk + 4]);   // {d0,d1}
                xp1[kk] = pack2(xs[kb + kk + 8], xs[kb + kk + 12]);  // {d2,d3}
            }
        }
        #pragma unroll
        for (int f = 0; f < 5; f++) {
            float4 wv = *(const float4*)(wr + f * 12 + kb);  // taps kb..kb+3 (pad 0 unused)
            float wk[4] = {wv.x, wv.y, wv.z, wv.w};
            #pragma unroll
            for (int kk = 0; kk < 4; kk++) {
                if (kk < ke) {
                    unsigned long long ww = pack2(wk[kk], wk[kk]);
                    fma2(acc[f][0], xp0[kk], ww);
                    fma2(acc[f][1], xp1[kk], ww);
                }
            }
        }
    }
}

__global__ void __launch_bounds__(256, 3)
cnn_kernel(const float* __restrict__ im,
           const float* __restrict__ w1,
           const float* __restrict__ w2,
           const float* __restrict__ b2,
           const float* __restrict__ lw,
           const float* __restrict__ lb,
           float* __restrict__ out)
{
    extern __shared__ float sm[];
    const int b   = blockIdx.x;
    const int tid = threadIdx.x;

    // ---- zero image + weight regions (halo & pad-lane correctness) ----
    for (int i = tid; i < SMEM_FLOATS; i += 256) sm[i] = 0.f;
    __syncthreads();

    {
        const float2* gim = (const float2*)(im + (size_t)b * 12288);
        for (int i = tid; i < 6144; i += 256) {
            float2 v = gim[i];
            int fi = i << 1;
            int c  = fi >> 12;
            int y  = (fi & 4095) >> 6;
            int x  = fi & 63;
            int base = c * IMCH + (y + 2) * IMROW + x + 2;
            sm[base]     = v.x;
            sm[base + 1] = v.y;
        }
    }
    // conv1 weights: [f][c][ky][kx] -> [c][ky][f][12] (pad lane kx=11 stays 0)
    for (int i = tid; i < 3630; i += 256) {
        int f   = i / 363;
        int rem = i % 363;
        int c   = rem / 121;
        int r2  = rem % 121;
        int ky  = r2 / 11;
        int kx  = r2 % 11;
        sm[S_W1 + ((c * 11 + ky) * 10 + f) * 12 + kx] = w1[i];
    }

    // graph half is analytically constant: softmax == 0.05 (verified exact R1-R16)
    if (tid < 20)
        out[b * 20 + tid] = 0.05f;

    __syncthreads();

    // ---- conv1 (11x11, s4, p2): 15x15 out, 10 filters, K-split across warp halves ----
    // group A = warps 0-3  (tid 0-119   active): rows c=0 ky0-10, c=1 ky0-4  (16)
    // group B = warps 4-7  (tid 128-247 active): rows c=1 ky5-10, c=2 ky0-10 (17)
    // within group: oy = a>>3 (0..14), pr = (a>>1)&3, fh = a&1
    // pixels ox = 4*pr+d (d=0..3, ox=15 discarded); filters fh*5..fh*5+4
    const bool grpB = (tid >= 128);
    const int  a    = grpB ? (tid - 128) : tid;
    const bool c1act = (a < 120);
    const int  oy = a >> 3, pr = (a >> 1) & 3, fh = a & 1;

    unsigned long long acc[5][2];
    #pragma unroll
    for (int f = 0; f < 5; f++) { acc[f][0] = 0ull; acc[f][1] = 0ull; }

    if (c1act) {
        if (!grpB) {
            #pragma unroll 1
            for (int ky = 0; ky < 11; ky++) c1_row(sm, 0, ky, oy, pr, fh, acc);
            #pragma unroll 1
            for (int ky = 0; ky < 5;  ky++) c1_row(sm, 1, ky, oy, pr, fh, acc);
        } else {
            #pragma unroll 1
            for (int ky = 5; ky < 11; ky++) c1_row(sm, 1, ky, oy, pr, fh, acc);
            #pragma unroll 1
            for (int ky = 0; ky < 11; ky++) c1_row(sm, 2, ky, oy, pr, fh, acc);
        }
    }
    __syncthreads();   // image reads done; region reusable

    // group B parks raw partials (d contiguous -> float4 at col 4*pr)
    if (grpB && c1act) {
        #pragma unroll
        for (int f = 0; f < 5; f++) {
            const int fg = fh * 5 + f;
            float d0, d1, d2, d3;
            unpack2(acc[f][0], d0, d1);
            unpack2(acc[f][1], d2, d3);
            *(float4*)&sm[S_TMP + (fg * 15 + oy) * 16 + 4 * pr] =
                make_float4(d0, d1, d2, d3);
        }
    }
    // stage conv2 weights padded [f][c][ky][8]
    for (int i = tid; i < 4000; i += 256) {
        int kx = i % 5; int t = i / 5;
        int ky = t % 5; t /= 5;
        int c  = t % 10; int f = t / 10;
        sm[S_W2P + (((f * 10 + c) * 5) + ky) * 8 + kx] = w2[i];
    }
    // zero-fill padded pool1 buffer
    for (int i = tid; i < 1320; i += 256)
        sm[S_P1P + i] = 0.f;
    __syncthreads();

    // group A combines + leaky -> C1 (col 15 = garbage, never read by pool)
    if (!grpB && c1act) {
        #pragma unroll
        for (int f = 0; f < 5; f++) {
            const int fg = fh * 5 + f;
            float d0, d1, d2, d3;
            unpack2(acc[f][0], d0, d1);
            unpack2(acc[f][1], d2, d3);
            float4 p = *(const float4*)&sm[S_TMP + (fg * 15 + oy) * 16 + 4 * pr];
            *(float4*)&sm[S_C1 + (fg * 15 + oy) * 16 + 4 * pr] =
                make_float4(leaky(d0 + p.x), leaky(d1 + p.y),
                            leaky(d2 + p.z), leaky(d3 + p.w));
        }
    }
    __syncthreads();

    // ---- maxpool 3x3 s2: 15x15 -> 7x7, write into zero-padded [10][11][12] ----
    for (int i = tid; i < 490; i += 256) {
        int f = i / 49, r = i % 49;
        int py = r / 7, px = r % 7;
        float m = -1e30f;
        #pragma unroll
        for (int dy = 0; dy < 3; dy++)
            #pragma unroll
            for (int dx = 0; dx < 3; dx++)
                m = fmaxf(m, sm[S_C1 + (f * 15 + (2 * py + dy)) * 16 + (2 * px + dx)]);
        sm[S_P1P + (f * 11 + py + 2) * 12 + px + 2] = m;
    }
    __syncthreads();

    // ---- conv2 (5x5, s2, p2): 7x7 -> 4x4, 10 -> 16 ch, guard-free ----
    {
        int f   = tid >> 4;
        int r   = tid & 15;
        int oy2 = r >> 2;
        int ox2 = r & 3;
        float av = b2[f];
        #pragma unroll 1
        for (int c = 0; c < 10; c++) {
            #pragma unroll
            for (int ky = 0; ky < 5; ky++) {
                const float* prow = &sm[S_P1P + (c * 11 + 2 * oy2 + ky) * 12 + 2 * ox2];
                const float4 wv = *(const float4*)&sm[S_W2P + ((f * 10 + c) * 5 + ky) * 8];
                const float  w4 = sm[S_W2P + ((f * 10 + c) * 5 + ky) * 8 + 4];
                av = fmaf(prow[0], wv.x, av);
                av = fmaf(prow[1], wv.y, av);
                av = fmaf(prow[2], wv.z, av);
                av = fmaf(prow[3], wv.w, av);
                av = fmaf(prow[4], w4,  av);
            }
        }
        sm[S_C2 + f * 16 + oy2 * 4 + ox2] = leaky(av);
    }
    __syncthreads();

    // ---- maxpool 2x2 s2: 4x4 -> 2x2, flatten ----
    if (tid < 64) {
        int f = tid >> 2, py = (tid >> 1) & 1, px = tid & 1;
        float m = sm[S_C2 + f * 16 + (2 * py) * 4 + (2 * px)];
        m = fmaxf(m, sm[S_C2 + f * 16 + (2 * py) * 4 + (2 * px + 1)]);
        m = fmaxf(m, sm[S_C2 + f * 16 + (2 * py + 1) * 4 + (2 * px)]);
        m = fmaxf(m, sm[S_C2 + f * 16 + (2 * py + 1) * 4 + (2 * px + 1)]);
        sm[S_FL + tid] = m;   // flat index == tid
    }
    __syncthreads();

    // ---- linear 64 -> 2 + sigmoid ----
    if (tid < 2) {
        float a2 = lb[tid];
        #pragma unroll
        for (int k = 0; k < 64; k++)
            a2 = fmaf(sm[S_FL + k], lw[tid * 64 + k], a2);
        out[NBATCH * 20 + b * 2 + tid] = 1.f / (1.f + __expf(-a2));
    }
}

extern "C" void kernel_launch(void* const* d_in, const int* in_sizes, int n_in,
                              void* d_out, int out_size)
{
    (void)in_sizes; (void)n_in; (void)out_size;
    const float* im = (const float*)d_in[0];
    // d_in[1] = x, d_in[2] = edge_index : dead (graph output is constant 0.05)
    const float* w1 = (const float*)d_in[3];
    const float* w2 = (const float*)d_in[4];
    const float* b2 = (const float*)d_in[5];
    const float* lw = (const float*)d_in[6];
    const float* lb = (const float*)d_in[7];
    float* out = (float*)d_out;

    cudaFuncSetAttribute(cnn_kernel, cudaFuncAttributeMaxDynamicSharedMemorySize,
                         SMEM_FLOATS * sizeof(float));
    cnn_kernel<<<NBATCH, 256, SMEM_FLOATS * sizeof(float)>>>(im, w1, w2, b2, lw, lb, out);
}